// round 1
// baseline (speedup 1.0000x reference)
#include <cuda_runtime.h>
#include <math.h>

// Problem constants
#define BB   2
#define SS   2048
#define DIM  2048
#define NH   16
#define DH   128
#define LKV  512
#define LQ   1024
#define MR   (BB*SS)    // 4096 rows when flattened [B*S, *]
#define HD   (NH*DH)    // 2048

// Static scratch (allocation-free rule: __device__ globals)
__device__ float g_cq [MR*(size_t)LQ];
__device__ float g_ckv[MR*(size_t)LKV];
__device__ float g_qa [MR*(size_t)HD];
__device__ float g_qr [MR*(size_t)HD];
__device__ float g_ka [MR*(size_t)HD];
__device__ float g_kr [MR*(size_t)HD];
__device__ float g_v  [MR*(size_t)HD];
__device__ float g_att[MR*(size_t)HD];
__device__ float g_sc [(size_t)BB*NH*SS*SS];   // 512 MB score scratch

// ---------------------------------------------------------------------------
// Generic tiled SGEMM: C = alpha * A(MxK) * op(B) [+ beta*C] [+ bias]
//   BT=true : B is [N,K] row-major (C = A*B^T)
//   BT=false: B is [K,N] row-major (C = A*B)
// Batched via grid.z: z -> (zb = z/Hdiv, zh = z%Hdiv), pointer offsets
// A += zb*sAb + zh*sAh, etc. M,N multiples of 128; K multiple of 8.
// ---------------------------------------------------------------------------
template <bool BT, bool BIAS, bool BETA>
__global__ __launch_bounds__(256)
void sgemm(int M, int N, int K,
           const float* __restrict__ A, int lda, long long sAb, long long sAh,
           const float* __restrict__ Bm, int ldb, long long sBb, long long sBh,
           float* __restrict__ C, int ldc, long long sCb, long long sCh,
           const float* __restrict__ bias, float alpha, int Hdiv)
{
    int z = blockIdx.z;
    int zb = z / Hdiv, zh = z - zb * Hdiv;
    A  += zb * sAb + zh * sAh;
    Bm += zb * sBb + zh * sBh;
    C  += zb * sCb + zh * sCh;

    __shared__ float As[8][128];
    __shared__ float Bs[8][128];

    const int tid = threadIdx.x;
    const int tx  = tid & 15;      // 16 col groups
    const int ty  = tid >> 4;      // 16 row groups

    float acc[8][8];
#pragma unroll
    for (int i = 0; i < 8; i++)
#pragma unroll
        for (int j = 0; j < 8; j++) acc[i][j] = 0.f;

    const int lRow = tid >> 1;          // 0..127
    const int lCol = (tid & 1) * 4;     // 0 or 4 (k offset)
    const float* Ap = A + (long long)(blockIdx.y * 128 + lRow) * lda + lCol;
    const float* Bp;
    if (BT) {
        Bp = Bm + (long long)(blockIdx.x * 128 + lRow) * ldb + lCol;
    } else {
        Bp = Bm + (long long)(tid >> 5) * ldb + blockIdx.x * 128 + (tid & 31) * 4;
    }

    for (int k0 = 0; k0 < K; k0 += 8) {
        float4 av = *(const float4*)(Ap + k0);
        As[lCol + 0][lRow] = av.x;
        As[lCol + 1][lRow] = av.y;
        As[lCol + 2][lRow] = av.z;
        As[lCol + 3][lRow] = av.w;
        if (BT) {
            float4 bv = *(const float4*)(Bp + k0);
            Bs[lCol + 0][lRow] = bv.x;
            Bs[lCol + 1][lRow] = bv.y;
            Bs[lCol + 2][lRow] = bv.z;
            Bs[lCol + 3][lRow] = bv.w;
        } else {
            float4 bv = *(const float4*)(Bp + (long long)k0 * ldb);
            *(float4*)&Bs[tid >> 5][(tid & 31) * 4] = bv;
        }
        __syncthreads();
#pragma unroll
        for (int k = 0; k < 8; k++) {
            float4 a0 = *(const float4*)&As[k][ty * 4];
            float4 a1 = *(const float4*)&As[k][64 + ty * 4];
            float4 b0 = *(const float4*)&Bs[k][tx * 4];
            float4 b1 = *(const float4*)&Bs[k][64 + tx * 4];
            float a[8] = {a0.x, a0.y, a0.z, a0.w, a1.x, a1.y, a1.z, a1.w};
            float b[8] = {b0.x, b0.y, b0.z, b0.w, b1.x, b1.y, b1.z, b1.w};
#pragma unroll
            for (int i = 0; i < 8; i++)
#pragma unroll
                for (int j = 0; j < 8; j++) acc[i][j] += a[i] * b[j];
        }
        __syncthreads();
    }

#pragma unroll
    for (int i = 0; i < 8; i++) {
        int r = blockIdx.y * 128 + (i < 4 ? ty * 4 + i : 64 + ty * 4 + (i - 4));
#pragma unroll
        for (int j = 0; j < 8; j++) {
            int c = blockIdx.x * 128 + (j < 4 ? tx * 4 + j : 64 + tx * 4 + (j - 4));
            float val = alpha * acc[i][j];
            if (BIAS) val += bias[c];
            long long idx = (long long)r * ldc + c;
            if (BETA) val += C[idx];
            C[idx] = val;
        }
    }
}

// ---------------------------------------------------------------------------
// RoPE in-place on a [B*S, H*DH] buffer. Pair i -> (d=2i, d=2i+1) within head.
// ---------------------------------------------------------------------------
__global__ void rope_kernel(float* __restrict__ t,
                            const float* __restrict__ fc,
                            const float* __restrict__ fs)
{
    long long idx = (long long)blockIdx.x * blockDim.x + threadIdx.x; // pair idx
    const long long total = (long long)MR * NH * (DH / 2);
    if (idx >= total) return;
    int i = (int)(idx & 63);              // DH/2 = 64
    long long t2 = idx >> 6;
    int h = (int)(t2 % NH);
    long long row = t2 / NH;              // b*S + s
    int s = (int)(row % SS);
    float c  = fc[s * 64 + i];
    float sn = fs[s * 64 + i];
    float* p = t + row * HD + h * DH + 2 * i;
    float e = p[0], o = p[1];
    p[0] = e * c - o * sn;
    p[1] = e * sn + o * c;
}

// ---------------------------------------------------------------------------
// Row softmax over contiguous rows of length ncols (fp32, in-place).
// ---------------------------------------------------------------------------
__global__ void softmax_rows(float* __restrict__ S, int ncols)
{
    long long row = blockIdx.x;
    float* p = S + row * (long long)ncols;
    __shared__ float red[256];
    int t = threadIdx.x;

    float m = -1e30f;
    for (int c = t; c < ncols; c += 256) m = fmaxf(m, p[c]);
    red[t] = m; __syncthreads();
    for (int s = 128; s > 0; s >>= 1) {
        if (t < s) red[t] = fmaxf(red[t], red[t + s]);
        __syncthreads();
    }
    m = red[0]; __syncthreads();

    float sum = 0.f;
    for (int c = t; c < ncols; c += 256) {
        float e = __expf(p[c] - m);
        p[c] = e;
        sum += e;
    }
    red[t] = sum; __syncthreads();
    for (int s = 128; s > 0; s >>= 1) {
        if (t < s) red[t] += red[t + s];
        __syncthreads();
    }
    float inv = 1.0f / red[0];
    for (int c = t; c < ncols; c += 256) p[c] *= inv;
}

// ---------------------------------------------------------------------------

extern "C" void kernel_launch(void* const* d_in, const int* in_sizes, int n_in,
                              void* d_out, int out_size)
{
    const float* x    = (const float*)d_in[0];
    const float* fc   = (const float*)d_in[1];
    const float* fs   = (const float*)d_in[2];
    const float* w_lq = (const float*)d_in[3];
    const float* w_lkv= (const float*)d_in[4];
    const float* w_q  = (const float*)d_in[5];
    const float* w_k  = (const float*)d_in[6];
    const float* w_v  = (const float*)d_in[7];
    const float* w_qr = (const float*)d_in[8];
    const float* b_qr = (const float*)d_in[9];
    const float* w_kr = (const float*)d_in[10];
    const float* b_kr = (const float*)d_in[11];
    const float* w_o  = (const float*)d_in[12];
    const float* b_o  = (const float*)d_in[13];
    float* out = (float*)d_out;

    float *cq, *ckv, *qa, *qr, *ka, *kr, *vv, *att, *sc;
    cudaGetSymbolAddress((void**)&cq,  g_cq);
    cudaGetSymbolAddress((void**)&ckv, g_ckv);
    cudaGetSymbolAddress((void**)&qa,  g_qa);
    cudaGetSymbolAddress((void**)&qr,  g_qr);
    cudaGetSymbolAddress((void**)&ka,  g_ka);
    cudaGetSymbolAddress((void**)&kr,  g_kr);
    cudaGetSymbolAddress((void**)&vv,  g_v);
    cudaGetSymbolAddress((void**)&att, g_att);
    cudaGetSymbolAddress((void**)&sc,  g_sc);

    const float scale = 0.08838834764831845f; // 1/sqrt(128)

    // --- projections ---
    // cq = x @ w_lq^T            [4096,1024]
    sgemm<true, false, false><<<dim3(LQ/128, MR/128, 1), 256>>>(
        MR, LQ, DIM, x, DIM, 0, 0, w_lq, DIM, 0, 0, cq, LQ, 0, 0, nullptr, 1.f, 1);
    // ckv = x @ w_lkv^T          [4096,512]
    sgemm<true, false, false><<<dim3(LKV/128, MR/128, 1), 256>>>(
        MR, LKV, DIM, x, DIM, 0, 0, w_lkv, DIM, 0, 0, ckv, LKV, 0, 0, nullptr, 1.f, 1);
    // qa = cq @ w_q^T            [4096,2048]
    sgemm<true, false, false><<<dim3(HD/128, MR/128, 1), 256>>>(
        MR, HD, LQ, cq, LQ, 0, 0, w_q, LQ, 0, 0, qa, HD, 0, 0, nullptr, 1.f, 1);
    // qr = cq @ w_qr^T + b_qr
    sgemm<true, true, false><<<dim3(HD/128, MR/128, 1), 256>>>(
        MR, HD, LQ, cq, LQ, 0, 0, w_qr, LQ, 0, 0, qr, HD, 0, 0, b_qr, 1.f, 1);
    // ka = ckv @ w_k^T
    sgemm<true, false, false><<<dim3(HD/128, MR/128, 1), 256>>>(
        MR, HD, LKV, ckv, LKV, 0, 0, w_k, LKV, 0, 0, ka, HD, 0, 0, nullptr, 1.f, 1);
    // kr = x @ w_kr^T + b_kr
    sgemm<true, true, false><<<dim3(HD/128, MR/128, 1), 256>>>(
        MR, HD, DIM, x, DIM, 0, 0, w_kr, DIM, 0, 0, kr, HD, 0, 0, b_kr, 1.f, 1);
    // v = ckv @ w_v^T
    sgemm<true, false, false><<<dim3(HD/128, MR/128, 1), 256>>>(
        MR, HD, LKV, ckv, LKV, 0, 0, w_v, LKV, 0, 0, vv, HD, 0, 0, nullptr, 1.f, 1);

    // --- RoPE on qr, kr ---
    {
        long long pairs = (long long)MR * NH * (DH / 2);
        int blocks = (int)((pairs + 255) / 256);
        rope_kernel<<<blocks, 256>>>(qr, fc, fs);
        rope_kernel<<<blocks, 256>>>(kr, fc, fs);
    }

    // --- attention scores: sc[z] = (qa.ka^T + qr.kr^T) * scale, z=(b,h) ---
    {
        long long sQb = (long long)SS * HD;   // per-batch stride in qa/ka
        long long sQh = DH;                   // per-head col offset
        long long sSb = (long long)NH * SS * SS;
        long long sSh = (long long)SS * SS;
        sgemm<true, false, false><<<dim3(SS/128, SS/128, BB*NH), 256>>>(
            SS, SS, DH, qa, HD, sQb, sQh, ka, HD, sQb, sQh,
            sc, SS, sSb, sSh, nullptr, scale, NH);
        sgemm<true, false, true><<<dim3(SS/128, SS/128, BB*NH), 256>>>(
            SS, SS, DH, qr, HD, sQb, sQh, kr, HD, sQb, sQh,
            sc, SS, sSb, sSh, nullptr, scale, NH);
    }

    // --- softmax over each score row ---
    softmax_rows<<<BB * NH * SS, 256>>>(sc, SS);

    // --- PV: att[b, q, h*128+d] = P[z] @ V[b,:,h,:]   (NN GEMM) ---
    {
        long long sSb = (long long)NH * SS * SS;
        long long sSh = (long long)SS * SS;
        long long sVb = (long long)SS * HD;
        long long sVh = DH;
        sgemm<false, false, false><<<dim3(DH/128, SS/128, BB*NH), 256>>>(
            SS, DH, SS, sc, SS, sSb, sSh, vv, HD, sVb, sVh,
            att, HD, sVb, sVh, nullptr, 1.f, NH);
    }

    // --- output projection: out = att @ w_o^T + b_o ---
    sgemm<true, true, false><<<dim3(DIM/128, MR/128, 1), 256>>>(
        MR, DIM, HD, att, HD, 0, 0, w_o, HD, 0, 0, out, DIM, 0, 0, b_o, 1.f, 1);

    (void)in_sizes; (void)n_in; (void)out_size;
}

// round 3
// speedup vs baseline: 2.3628x; 2.3628x over previous
#include <cuda_runtime.h>
#include <cuda_bf16.h>
#include <cstdint>

// Problem constants
#define BB   2
#define SS   2048
#define DIM  2048
#define NH   16
#define DH   128
#define LKV  512
#define LQ   1024
#define MR   (BB*SS)    // 4096
#define HD   (NH*DH)    // 2048

// Static scratch
__device__ float g_cq [MR*(size_t)LQ];
__device__ float g_ckv[MR*(size_t)LKV];
__device__ float g_qa [MR*(size_t)HD];
__device__ float g_qr [MR*(size_t)HD];
__device__ float g_ka [MR*(size_t)HD];
__device__ float g_kr [MR*(size_t)HD];
__device__ float g_v  [MR*(size_t)HD];
__device__ float g_vt [(size_t)BB*NH*DH*SS];   // V transposed per (b,h): [d][s]
__device__ float g_att[MR*(size_t)HD];
__device__ float g_sc [(size_t)BB*NH*SS*SS];   // 512 MB score scratch

// ---------------------------------------------------------------------------
// Helpers
// ---------------------------------------------------------------------------
__device__ __forceinline__ uint32_t smem_u32(const void* p) {
    uint32_t a;
    asm("{ .reg .u64 t; cvta.to.shared.u64 t, %1; cvt.u32.u64 %0, t; }" : "=r"(a) : "l"(p));
    return a;
}

__device__ __forceinline__ void ldm_x4(uint32_t addr, uint32_t r[4]) {
    asm volatile("ldmatrix.sync.aligned.m8n8.x4.shared.b16 {%0,%1,%2,%3}, [%4];"
                 : "=r"(r[0]), "=r"(r[1]), "=r"(r[2]), "=r"(r[3]) : "r"(addr));
}

__device__ __forceinline__ void mma16816(float c[4], const uint32_t a[4],
                                         uint32_t b0, uint32_t b1) {
    asm volatile(
        "mma.sync.aligned.m16n8k16.row.col.f32.bf16.bf16.f32 "
        "{%0,%1,%2,%3}, {%4,%5,%6,%7}, {%8,%9}, {%0,%1,%2,%3};"
        : "+f"(c[0]), "+f"(c[1]), "+f"(c[2]), "+f"(c[3])
        : "r"(a[0]), "r"(a[1]), "r"(a[2]), "r"(a[3]), "r"(b0), "r"(b1));
}

// pack two fp32 -> bf16x2 {lower=a, upper=b}
__device__ __forceinline__ uint32_t packbf(float a, float b) {
    uint32_t r;
    asm("cvt.rn.satfinite.bf16x2.f32 %0, %1, %2;" : "=r"(r) : "f"(b), "f"(a));
    return r;
}
__device__ __forceinline__ float lo_of(uint32_t h) { return __uint_as_float(h << 16); }
__device__ __forceinline__ float hi_of(uint32_t h) { return __uint_as_float(h & 0xFFFF0000u); }

__device__ __forceinline__ void sts_v4(uint32_t addr, uint4 v) {
    asm volatile("st.shared.v4.b32 [%0], {%1,%2,%3,%4};"
                 :: "r"(addr), "r"(v.x), "r"(v.y), "r"(v.z), "r"(v.w) : "memory");
}

// SMEM layout: per stage: A_hi, A_lo, B_hi, B_lo tiles of 128 rows x 80B pitch
#define PITCH    80
#define TILE_SZ  (128*PITCH)    // 10240
#define OF_AHI   0
#define OF_ALO   10240
#define OF_BHI   20480
#define OF_BLO   30720
#define STAGE_SZ 40960
#define SMEMSZ   81920

// ---------------------------------------------------------------------------
// Warp-MMA GEMM: C = alpha * A * B^T [+ bias]
//   A [M,K] row-major (lda), B [N,K] row-major (ldb), C [M,N] (ldc)
//   DUAL: continue accumulating A2 * B2^T (same shapes) before epilogue
//   Batched via grid.z: z -> (zb=z/Hdiv, zh=z%Hdiv), pointer offsets.
//   Grid: (N/128, M/128, Z), block = 512 threads (16 warps, 32x32 warp tiles).
//   K multiple of 32. bf16 hi/lo split, 3-product fp32-accurate emulation.
// ---------------------------------------------------------------------------
template<bool BIAS, bool DUAL>
__global__ __launch_bounds__(512)
void tgemm(int K,
           const float* __restrict__ A, int lda, long long sAb, long long sAh,
           const float* __restrict__ Bm, int ldb, long long sBb, long long sBh,
           const float* __restrict__ A2, const float* __restrict__ B2,
           float* __restrict__ C, int ldc, long long sCb, long long sCh,
           const float* __restrict__ bias, float alpha, int Hdiv)
{
    extern __shared__ __align__(128) char smc[];
    const uint32_t smb = smem_u32(smc);
    const int tid  = threadIdx.x;
    const int lane = tid & 31;
    const int wid  = tid >> 5;
    const int wm   = (wid & 3) * 32;   // warp M offset in 128
    const int wn   = (wid >> 2) * 32;  // warp N offset in 128

    int z = blockIdx.z;
    int zb = z / Hdiv, zh = z - zb * Hdiv;
    A  += zb * sAb + zh * sAh;
    Bm += zb * sBb + zh * sBh;
    if (DUAL) { A2 += zb * sAb + zh * sAh; B2 += zb * sBb + zh * sBh; }
    C  += zb * sCb + zh * sCh;

    // global staging mapping: 512 threads cover 128 rows x 32 k (8 floats each)
    const int arow = tid >> 2;
    const int ako  = (tid & 3) * 8;
    const long long aoff = (long long)(blockIdx.y * 128 + arow) * lda;
    const long long boff = (long long)(blockIdx.x * 128 + arow) * ldb;

    float acc[2][4][4];
#pragma unroll
    for (int i = 0; i < 2; i++)
#pragma unroll
        for (int j = 0; j < 4; j++)
#pragma unroll
            for (int k = 0; k < 4; k++) acc[i][j][k] = 0.f;

    const int nch   = K >> 5;
    const int total = DUAL ? nch * 2 : nch;

    float4 ra0, ra1, rb0, rb1;

    // --- helpers as lambdas ---
    auto LDG = [&](int c) {
        const float* Ap = A; const float* Bp = Bm; int cc = c;
        if (DUAL && c >= nch) { Ap = A2; Bp = B2; cc = c - nch; }
        const float* pa = Ap + aoff + cc * 32 + ako;
        const float* pb = Bp + boff + cc * 32 + ako;
        ra0 = *(const float4*)pa; ra1 = *(const float4*)(pa + 4);
        rb0 = *(const float4*)pb; rb1 = *(const float4*)(pb + 4);
    };

    auto STS = [&](int s) {
        const uint32_t base = smb + s * STAGE_SZ + arow * PITCH + ako * 2;
        // A
        uint4 hi, lo;
        hi.x = packbf(ra0.x, ra0.y); hi.y = packbf(ra0.z, ra0.w);
        hi.z = packbf(ra1.x, ra1.y); hi.w = packbf(ra1.z, ra1.w);
        lo.x = packbf(ra0.x - lo_of(hi.x), ra0.y - hi_of(hi.x));
        lo.y = packbf(ra0.z - lo_of(hi.y), ra0.w - hi_of(hi.y));
        lo.z = packbf(ra1.x - lo_of(hi.z), ra1.y - hi_of(hi.z));
        lo.w = packbf(ra1.z - lo_of(hi.w), ra1.w - hi_of(hi.w));
        sts_v4(base + OF_AHI, hi);
        sts_v4(base + OF_ALO, lo);
        // B
        hi.x = packbf(rb0.x, rb0.y); hi.y = packbf(rb0.z, rb0.w);
        hi.z = packbf(rb1.x, rb1.y); hi.w = packbf(rb1.z, rb1.w);
        lo.x = packbf(rb0.x - lo_of(hi.x), rb0.y - hi_of(hi.x));
        lo.y = packbf(rb0.z - lo_of(hi.y), rb0.w - hi_of(hi.y));
        lo.z = packbf(rb1.x - lo_of(hi.z), rb1.y - hi_of(hi.z));
        lo.w = packbf(rb1.z - lo_of(hi.w), rb1.w - hi_of(hi.w));
        sts_v4(base + OF_BHI, hi);
        sts_v4(base + OF_BLO, lo);
    };

    auto COMPUTE = [&](int s) {
        const uint32_t sa = smb + s * STAGE_SZ;
#pragma unroll
        for (int ks = 0; ks < 2; ++ks) {
            const uint32_t colb = ks * 32;
            uint32_t ahi[2][4], alo[2][4], bhi[2][4], blo[2][4];
#pragma unroll
            for (int mt = 0; mt < 2; ++mt) {
                uint32_t addr = sa + OF_AHI +
                    (wm + mt * 16 + (lane & 15)) * PITCH + colb + (lane >> 4) * 16;
                ldm_x4(addr, ahi[mt]);
                ldm_x4(addr + (OF_ALO - OF_AHI), alo[mt]);
            }
#pragma unroll
            for (int np = 0; np < 2; ++np) {
                uint32_t addr = sa + OF_BHI +
                    (wn + np * 16 + (lane & 7) + ((lane >> 4) << 3)) * PITCH +
                    colb + ((lane >> 3) & 1) * 16;
                ldm_x4(addr, bhi[np]);
                ldm_x4(addr + (OF_BLO - OF_BHI), blo[np]);
            }
#pragma unroll
            for (int mt = 0; mt < 2; ++mt)
#pragma unroll
                for (int nt = 0; nt < 4; ++nt) {
                    uint32_t b0h = bhi[nt >> 1][(nt & 1) * 2];
                    uint32_t b1h = bhi[nt >> 1][(nt & 1) * 2 + 1];
                    uint32_t b0l = blo[nt >> 1][(nt & 1) * 2];
                    uint32_t b1l = blo[nt >> 1][(nt & 1) * 2 + 1];
                    mma16816(acc[mt][nt], ahi[mt], b0h, b1h);
                    mma16816(acc[mt][nt], ahi[mt], b0l, b1l);
                    mma16816(acc[mt][nt], alo[mt], b0h, b1h);
                }
        }
    };

    // --- software pipeline: one sync per chunk ---
    LDG(0);
    STS(0);
    __syncthreads();
    for (int c = 0; c < total; ++c) {
        if (c + 1 < total) LDG(c + 1);
        COMPUTE(c & 1);
        if (c + 1 < total) STS((c + 1) & 1);
        __syncthreads();
    }

    // --- epilogue ---
    const int g = lane >> 2, t = lane & 3;
#pragma unroll
    for (int mt = 0; mt < 2; ++mt) {
        const int r0 = blockIdx.y * 128 + wm + mt * 16 + g;
#pragma unroll
        for (int nt = 0; nt < 4; ++nt) {
            const int col = blockIdx.x * 128 + wn + nt * 8 + t * 2;
            float b0 = 0.f, b1 = 0.f;
            if (BIAS) { b0 = bias[col]; b1 = bias[col + 1]; }
            float2 v0, v1;
            v0.x = alpha * acc[mt][nt][0] + b0;
            v0.y = alpha * acc[mt][nt][1] + b1;
            v1.x = alpha * acc[mt][nt][2] + b0;
            v1.y = alpha * acc[mt][nt][3] + b1;
            *(float2*)&C[(long long)r0 * ldc + col] = v0;
            *(float2*)&C[(long long)(r0 + 8) * ldc + col] = v1;
        }
    }
}

// ---------------------------------------------------------------------------
// Transpose V: vt[(b*NH+h)*DH + d][s] = v[(b*SS+s)*HD + h*DH + d]
// ---------------------------------------------------------------------------
__global__ void transpose_v(const float* __restrict__ v, float* __restrict__ vt)
{
    __shared__ float t[32][33];
    int z = blockIdx.z;               // b*NH + h
    int b = z / NH, h = z - b * NH;
    int s0 = blockIdx.y * 32, d0 = blockIdx.x * 32;
    int x = threadIdx.x, y = threadIdx.y;   // 32 x 8
#pragma unroll
    for (int i = 0; i < 32; i += 8)
        t[y + i][x] = v[((long long)(b * SS + s0 + y + i)) * HD + h * DH + d0 + x];
    __syncthreads();
#pragma unroll
    for (int i = 0; i < 32; i += 8)
        vt[((long long)(z * DH + d0 + y + i)) * SS + s0 + x] = t[x][y + i];
}

// ---------------------------------------------------------------------------
// RoPE in-place on a [B*S, H*DH] buffer.
// ---------------------------------------------------------------------------
__global__ void rope_kernel(float* __restrict__ t,
                            const float* __restrict__ fc,
                            const float* __restrict__ fs)
{
    long long idx = (long long)blockIdx.x * blockDim.x + threadIdx.x;
    const long long total = (long long)MR * NH * (DH / 2);
    if (idx >= total) return;
    int i = (int)(idx & 63);
    long long t2 = idx >> 6;
    int h = (int)(t2 % NH);
    long long row = t2 / NH;
    int s = (int)(row % SS);
    float c  = fc[s * 64 + i];
    float sn = fs[s * 64 + i];
    float* p = t + row * HD + h * DH + 2 * i;
    float e = p[0], o = p[1];
    p[0] = e * c - o * sn;
    p[1] = e * sn + o * c;
}

// ---------------------------------------------------------------------------
// Row softmax (fp32, in-place)
// ---------------------------------------------------------------------------
__global__ void softmax_rows(float* __restrict__ S, int ncols)
{
    long long row = blockIdx.x;
    float* p = S + row * (long long)ncols;
    __shared__ float red[256];
    int t = threadIdx.x;

    float m = -1e30f;
    for (int c = t; c < ncols; c += 256) m = fmaxf(m, p[c]);
    red[t] = m; __syncthreads();
    for (int s = 128; s > 0; s >>= 1) {
        if (t < s) red[t] = fmaxf(red[t], red[t + s]);
        __syncthreads();
    }
    m = red[0]; __syncthreads();

    float sum = 0.f;
    for (int c = t; c < ncols; c += 256) {
        float e = __expf(p[c] - m);
        p[c] = e;
        sum += e;
    }
    red[t] = sum; __syncthreads();
    for (int s = 128; s > 0; s >>= 1) {
        if (t < s) red[t] += red[t + s];
        __syncthreads();
    }
    float inv = 1.0f / red[0];
    for (int c = t; c < ncols; c += 256) p[c] *= inv;
}

// ---------------------------------------------------------------------------

extern "C" void kernel_launch(void* const* d_in, const int* in_sizes, int n_in,
                              void* d_out, int out_size)
{
    const float* x    = (const float*)d_in[0];
    const float* fc   = (const float*)d_in[1];
    const float* fs   = (const float*)d_in[2];
    const float* w_lq = (const float*)d_in[3];
    const float* w_lkv= (const float*)d_in[4];
    const float* w_q  = (const float*)d_in[5];
    const float* w_k  = (const float*)d_in[6];
    const float* w_v  = (const float*)d_in[7];
    const float* w_qr = (const float*)d_in[8];
    const float* b_qr = (const float*)d_in[9];
    const float* w_kr = (const float*)d_in[10];
    const float* b_kr = (const float*)d_in[11];
    const float* w_o  = (const float*)d_in[12];
    const float* b_o  = (const float*)d_in[13];
    float* out = (float*)d_out;

    float *cq, *ckv, *qa, *qr, *ka, *kr, *vv, *vt, *att, *sc;
    cudaGetSymbolAddress((void**)&cq,  g_cq);
    cudaGetSymbolAddress((void**)&ckv, g_ckv);
    cudaGetSymbolAddress((void**)&qa,  g_qa);
    cudaGetSymbolAddress((void**)&qr,  g_qr);
    cudaGetSymbolAddress((void**)&ka,  g_ka);
    cudaGetSymbolAddress((void**)&kr,  g_kr);
    cudaGetSymbolAddress((void**)&vv,  g_v);
    cudaGetSymbolAddress((void**)&vt,  g_vt);
    cudaGetSymbolAddress((void**)&att, g_att);
    cudaGetSymbolAddress((void**)&sc,  g_sc);

    static bool attr_done = false;
    if (!attr_done) {
        cudaFuncSetAttribute(tgemm<false, false>, cudaFuncAttributeMaxDynamicSharedMemorySize, SMEMSZ);
        cudaFuncSetAttribute(tgemm<true,  false>, cudaFuncAttributeMaxDynamicSharedMemorySize, SMEMSZ);
        cudaFuncSetAttribute(tgemm<false, true >, cudaFuncAttributeMaxDynamicSharedMemorySize, SMEMSZ);
        attr_done = true;
    }

    const float scale = 0.08838834764831845f; // 1/sqrt(128)

    // --- projections (all A[M,K] * B[N,K]^T) ---
    // cq = x @ w_lq^T
    tgemm<false, false><<<dim3(LQ/128, MR/128, 1), 512, SMEMSZ>>>(
        DIM, x, DIM, 0, 0, w_lq, DIM, 0, 0, nullptr, nullptr,
        cq, LQ, 0, 0, nullptr, 1.f, 1);
    // ckv = x @ w_lkv^T
    tgemm<false, false><<<dim3(LKV/128, MR/128, 1), 512, SMEMSZ>>>(
        DIM, x, DIM, 0, 0, w_lkv, DIM, 0, 0, nullptr, nullptr,
        ckv, LKV, 0, 0, nullptr, 1.f, 1);
    // qa = cq @ w_q^T
    tgemm<false, false><<<dim3(HD/128, MR/128, 1), 512, SMEMSZ>>>(
        LQ, cq, LQ, 0, 0, w_q, LQ, 0, 0, nullptr, nullptr,
        qa, HD, 0, 0, nullptr, 1.f, 1);
    // qr = cq @ w_qr^T + b_qr
    tgemm<true, false><<<dim3(HD/128, MR/128, 1), 512, SMEMSZ>>>(
        LQ, cq, LQ, 0, 0, w_qr, LQ, 0, 0, nullptr, nullptr,
        qr, HD, 0, 0, b_qr, 1.f, 1);
    // ka = ckv @ w_k^T
    tgemm<false, false><<<dim3(HD/128, MR/128, 1), 512, SMEMSZ>>>(
        LKV, ckv, LKV, 0, 0, w_k, LKV, 0, 0, nullptr, nullptr,
        ka, HD, 0, 0, nullptr, 1.f, 1);
    // kr = x @ w_kr^T + b_kr
    tgemm<true, false><<<dim3(HD/128, MR/128, 1), 512, SMEMSZ>>>(
        DIM, x, DIM, 0, 0, w_kr, DIM, 0, 0, nullptr, nullptr,
        kr, HD, 0, 0, b_kr, 1.f, 1);
    // v = ckv @ w_v^T
    tgemm<false, false><<<dim3(HD/128, MR/128, 1), 512, SMEMSZ>>>(
        LKV, ckv, LKV, 0, 0, w_v, LKV, 0, 0, nullptr, nullptr,
        vv, HD, 0, 0, nullptr, 1.f, 1);

    // --- RoPE on qr, kr ---
    {
        long long pairs = (long long)MR * NH * (DH / 2);
        int blocks = (int)((pairs + 255) / 256);
        rope_kernel<<<blocks, 256>>>(qr, fc, fs);
        rope_kernel<<<blocks, 256>>>(kr, fc, fs);
    }

    // --- transpose V for PV GEMM ---
    transpose_v<<<dim3(DH/32, SS/32, BB*NH), dim3(32, 8)>>>(vv, vt);

    // --- scores: sc[z] = (qa.ka^T + qr.kr^T) * scale  (DUAL accumulation) ---
    {
        long long sQb = (long long)SS * HD;
        long long sQh = DH;
        long long sSb = (long long)NH * SS * SS;
        long long sSh = (long long)SS * SS;
        tgemm<false, true><<<dim3(SS/128, SS/128, BB*NH), 512, SMEMSZ>>>(
            DH, qa, HD, sQb, sQh, ka, HD, sQb, sQh, qr, kr,
            sc, SS, sSb, sSh, nullptr, scale, NH);
    }

    // --- softmax ---
    softmax_rows<<<BB * NH * SS, 256>>>(sc, SS);

    // --- PV: att[q, h*DH+d] = P[z] @ vt[z]^T  (NT form via transposed V) ---
    {
        long long sSb = (long long)NH * SS * SS;
        long long sSh = (long long)SS * SS;
        long long sVtb = (long long)NH * DH * SS;   // vt batch stride
        long long sVth = (long long)DH * SS;        // vt head stride
        long long sCb = (long long)SS * HD;
        long long sCh = DH;
        tgemm<false, false><<<dim3(DH/128, SS/128, BB*NH), 512, SMEMSZ>>>(
            SS, sc, SS, sSb, sSh, vt, SS, sVtb, sVth, nullptr, nullptr,
            att, HD, sCb, sCh, nullptr, 1.f, NH);
    }

    // --- out = att @ w_o^T + b_o ---
    tgemm<true, false><<<dim3(DIM/128, MR/128, 1), 512, SMEMSZ>>>(
        HD, att, HD, 0, 0, w_o, HD, 0, 0, nullptr, nullptr,
        out, DIM, 0, 0, b_o, 1.f, 1);

    (void)in_sizes; (void)n_in; (void)out_size;
}